// round 1
// baseline (speedup 1.0000x reference)
#include <cuda_runtime.h>
#include <math.h>

// Problem constants
#define S_LEN   2048
#define HIDDEN  2048
#define NH      16
#define HD      128
#define RD      64
#define KVC     512
#define QCDIM   1024
#define DQK     192   // HD + RD

// ---------------------------------------------------------------------------
// Scratch buffers (static device allocations; no cudaMalloc allowed)
// ---------------------------------------------------------------------------
__device__ float g_kvc[S_LEN * KVC];          // kv compressed        [s, 512]
__device__ float g_qc [S_LEN * QCDIM];        // q compressed         [s, 1024]
__device__ float g_kc [S_LEN * NH * HD];      // keys_c               [s, 2048]
__device__ float g_kr [S_LEN * NH * RD];      // keys_rope (pre-rope) [s, 1024]
__device__ float g_qcu[S_LEN * NH * HD];      // queries_c            [s, 2048]
__device__ float g_qr [S_LEN * NH * RD];      // queries_rope         [s, 1024]
__device__ float g_Kb [S_LEN * NH * DQK];     // concat K             [s, h*192+d]
__device__ float g_Qb [S_LEN * NH * DQK];     // concat Q
__device__ float g_V  [S_LEN * NH * HD];      // values               [s, 2048]
__device__ float g_Sc [(size_t)NH * S_LEN * S_LEN];   // scores/probs [h, q, k]
__device__ float g_ctx[S_LEN * NH * HD];      // context              [s, 2048]

// ---------------------------------------------------------------------------
// Generic tiled SGEMM:  C = alpha * A @ op(B) + bias
//   A: [M,K] row-major, lda
//   BT=true : B is [N,K] row-major (compute A @ B^T)   -- weights / K for QK^T
//   BT=false: B is [K,N] row-major (compute A @ B)     -- V for P@V
//   Batched via grid.z with element strides sA/sB/sC.
//   Requires: M%128==0, N%128==0, K%8==0 (true for all shapes here).
// ---------------------------------------------------------------------------
template<bool BT>
__global__ void __launch_bounds__(256, 2) sgemm_kernel(
    const float* __restrict__ A, const float* __restrict__ B,
    const float* __restrict__ bias, float* __restrict__ C,
    int M, int N, int K, int lda, int ldb, int ldc,
    long long sA, long long sB, long long sC, float alpha)
{
    const int bz = blockIdx.z;
    A += (long long)bz * sA;
    B += (long long)bz * sB;
    C += (long long)bz * sC;

    __shared__ float As[8][128];   // transposed: As[k][m]
    __shared__ float Bs[8][128];   // Bs[k][n]

    const int tid = threadIdx.x;
    const int tx  = tid & 15;        // 0..15 (col group)
    const int ty  = tid >> 4;        // 0..15 (row group)

    const int mBase = blockIdx.y * 128;
    const int nBase = blockIdx.x * 128;

    // A-tile load mapping: 128 rows x 8 cols -> one float4 per thread
    const int la_row = tid >> 1;          // 0..127
    const int la_k   = (tid & 1) * 4;     // 0 or 4

    float acc[8][8];
    #pragma unroll
    for (int i = 0; i < 8; i++)
        #pragma unroll
        for (int j = 0; j < 8; j++) acc[i][j] = 0.f;

    for (int k0 = 0; k0 < K; k0 += 8) {
        // --- load A tile (transposed into smem) ---
        {
            const float4 a4 = *(const float4*)(A + (long long)(mBase + la_row) * lda + k0 + la_k);
            As[la_k + 0][la_row] = a4.x;
            As[la_k + 1][la_row] = a4.y;
            As[la_k + 2][la_row] = a4.z;
            As[la_k + 3][la_row] = a4.w;
        }
        // --- load B tile ---
        if (BT) {
            const float4 b4 = *(const float4*)(B + (long long)(nBase + la_row) * ldb + k0 + la_k);
            Bs[la_k + 0][la_row] = b4.x;
            Bs[la_k + 1][la_row] = b4.y;
            Bs[la_k + 2][la_row] = b4.z;
            Bs[la_k + 3][la_row] = b4.w;
        } else {
            const int kk = tid >> 5;           // 0..7
            const int nn = (tid & 31) * 4;     // 0..124
            const float4 b4 = *(const float4*)(B + (long long)(k0 + kk) * ldb + nBase + nn);
            *(float4*)&Bs[kk][nn] = b4;
        }
        __syncthreads();

        #pragma unroll
        for (int k = 0; k < 8; k++) {
            float af[8], bf[8];
            *(float4*)(af)     = *(const float4*)&As[k][ty * 8];
            *(float4*)(af + 4) = *(const float4*)&As[k][ty * 8 + 4];
            *(float4*)(bf)     = *(const float4*)&Bs[k][tx * 8];
            *(float4*)(bf + 4) = *(const float4*)&Bs[k][tx * 8 + 4];
            #pragma unroll
            for (int i = 0; i < 8; i++)
                #pragma unroll
                for (int j = 0; j < 8; j++)
                    acc[i][j] = fmaf(af[i], bf[j], acc[i][j]);
        }
        __syncthreads();
    }

    // --- epilogue ---
    #pragma unroll
    for (int i = 0; i < 8; i++) {
        const long long row = mBase + ty * 8 + i;
        #pragma unroll
        for (int j = 0; j < 8; j += 4) {
            const int col = nBase + tx * 8 + j;
            float4 v;
            v.x = acc[i][j + 0] * alpha;
            v.y = acc[i][j + 1] * alpha;
            v.z = acc[i][j + 2] * alpha;
            v.w = acc[i][j + 3] * alpha;
            if (bias) {
                v.x += bias[col + 0];
                v.y += bias[col + 1];
                v.z += bias[col + 2];
                v.w += bias[col + 3];
            }
            *(float4*)(C + row * (long long)ldc + col) = v;
        }
    }
}

// ---------------------------------------------------------------------------
// Assemble concat buffer [s, h, 192]: cols 0..127 from comp, 128..191 roped.
// RoPE positions = head index (faithful to reference's axis choice).
// ---------------------------------------------------------------------------
__global__ void assemble_rope_kernel(const float* __restrict__ comp,
                                     const float* __restrict__ rope,
                                     float* __restrict__ out)
{
    const int idx = blockIdx.x * blockDim.x + threadIdx.x;
    if (idx >= S_LEN * NH * DQK) return;
    const int s = idx / (NH * DQK);
    const int c = idx - s * (NH * DQK);
    const int h = c / DQK;
    const int d = c - h * DQK;
    float val;
    if (d < HD) {
        val = comp[s * (NH * HD) + h * HD + d];
    } else {
        const int r = d - HD;           // 0..63
        const int j = r >> 1;           // pair index 0..31
        const float inv_freq = powf(10000.f, -(2.f * j) / (float)RD);
        const float ang = (float)h * inv_freq;
        const float sn = sinf(ang), cs = cosf(ang);
        const int base = s * (NH * RD) + h * RD + 2 * j;
        const float x1 = rope[base];
        const float x2 = rope[base + 1];
        val = (r & 1) ? (x1 * sn + x2 * cs) : (x1 * cs - x2 * sn);
    }
    out[idx] = val;
}

// ---------------------------------------------------------------------------
// Row softmax over S_LEN=2048 elements. One 256-thread block per row.
// ---------------------------------------------------------------------------
__global__ void softmax_kernel(float* __restrict__ Sc)
{
    float* p = Sc + (long long)blockIdx.x * S_LEN;
    const int tid = threadIdx.x;
    __shared__ float red[256];

    float v[8];
    float lm = -INFINITY;
    #pragma unroll
    for (int i = 0; i < 8; i++) {
        v[i] = p[tid + i * 256];
        lm = fmaxf(lm, v[i]);
    }
    red[tid] = lm;
    __syncthreads();
    #pragma unroll
    for (int s = 128; s > 0; s >>= 1) {
        if (tid < s) red[tid] = fmaxf(red[tid], red[tid + s]);
        __syncthreads();
    }
    const float m = red[0];
    __syncthreads();

    float ls = 0.f;
    #pragma unroll
    for (int i = 0; i < 8; i++) {
        v[i] = expf(v[i] - m);
        ls += v[i];
    }
    red[tid] = ls;
    __syncthreads();
    #pragma unroll
    for (int s = 128; s > 0; s >>= 1) {
        if (tid < s) red[tid] += red[tid + s];
        __syncthreads();
    }
    const float inv = 1.f / red[0];
    #pragma unroll
    for (int i = 0; i < 8; i++) p[tid + i * 256] = v[i] * inv;
}

// ---------------------------------------------------------------------------
// Host-side launch helpers
// ---------------------------------------------------------------------------
static void gemm_nt(float* C, const float* A, const float* B, const float* bias,
                    int M, int N, int K, int lda, int ldb, int ldc,
                    float alpha = 1.f, int batch = 1,
                    long long sA = 0, long long sB = 0, long long sC = 0)
{
    dim3 grid(N / 128, M / 128, batch);
    sgemm_kernel<true><<<grid, 256>>>(A, B, bias, C, M, N, K, lda, ldb, ldc,
                                      sA, sB, sC, alpha);
}

static void gemm_nn(float* C, const float* A, const float* B, const float* bias,
                    int M, int N, int K, int lda, int ldb, int ldc,
                    float alpha = 1.f, int batch = 1,
                    long long sA = 0, long long sB = 0, long long sC = 0)
{
    dim3 grid(N / 128, M / 128, batch);
    sgemm_kernel<false><<<grid, 256>>>(A, B, bias, C, M, N, K, lda, ldb, ldc,
                                       sA, sB, sC, alpha);
}

extern "C" void kernel_launch(void* const* d_in, const int* in_sizes, int n_in,
                              void* d_out, int out_size)
{
    const float* x            = (const float*)d_in[0];
    const float* kv_down_w    = (const float*)d_in[1];
    const float* kv_down_b    = (const float*)d_in[2];
    const float* key_up_w     = (const float*)d_in[3];
    const float* key_up_b     = (const float*)d_in[4];
    const float* value_up_w   = (const float*)d_in[5];
    const float* value_up_b   = (const float*)d_in[6];
    const float* key_rope_w   = (const float*)d_in[7];
    const float* key_rope_b   = (const float*)d_in[8];
    const float* query_down_w = (const float*)d_in[9];
    const float* query_down_b = (const float*)d_in[10];
    const float* query_up_w   = (const float*)d_in[11];
    const float* query_up_b   = (const float*)d_in[12];
    const float* query_rope_w = (const float*)d_in[13];
    const float* query_rope_b = (const float*)d_in[14];
    const float* out_w        = (const float*)d_in[15];
    const float* out_b        = (const float*)d_in[16];
    float* out = (float*)d_out;

    float *kvc, *qc, *kc, *kr, *qcu, *qr, *Kb, *Qb, *V, *Sc, *ctx;
    cudaGetSymbolAddress((void**)&kvc, g_kvc);
    cudaGetSymbolAddress((void**)&qc,  g_qc);
    cudaGetSymbolAddress((void**)&kc,  g_kc);
    cudaGetSymbolAddress((void**)&kr,  g_kr);
    cudaGetSymbolAddress((void**)&qcu, g_qcu);
    cudaGetSymbolAddress((void**)&qr,  g_qr);
    cudaGetSymbolAddress((void**)&Kb,  g_Kb);
    cudaGetSymbolAddress((void**)&Qb,  g_Qb);
    cudaGetSymbolAddress((void**)&V,   g_V);
    cudaGetSymbolAddress((void**)&Sc,  g_Sc);
    cudaGetSymbolAddress((void**)&ctx, g_ctx);

    // 1. down projections
    gemm_nt(kvc, x, kv_down_w, kv_down_b, S_LEN, KVC,   HIDDEN, HIDDEN, HIDDEN, KVC);
    gemm_nt(qc,  x, query_down_w, query_down_b, S_LEN, QCDIM, HIDDEN, HIDDEN, HIDDEN, QCDIM);

    // 2. up projections
    gemm_nt(kc,  kvc, key_up_w,    key_up_b,    S_LEN, NH * HD, KVC,   KVC,   KVC,   NH * HD);
    gemm_nt(V,   kvc, value_up_w,  value_up_b,  S_LEN, NH * HD, KVC,   KVC,   KVC,   NH * HD);
    gemm_nt(kr,  kvc, key_rope_w,  key_rope_b,  S_LEN, NH * RD, KVC,   KVC,   KVC,   NH * RD);
    gemm_nt(qcu, qc,  query_up_w,  query_up_b,  S_LEN, NH * HD, QCDIM, QCDIM, QCDIM, NH * HD);
    gemm_nt(qr,  qc,  query_rope_w, query_rope_b, S_LEN, NH * RD, QCDIM, QCDIM, QCDIM, NH * RD);

    // 3. rope + concat into [s, h, 192]
    {
        const int total = S_LEN * NH * DQK;
        const int nb = (total + 255) / 256;
        assemble_rope_kernel<<<nb, 256>>>(kc,  kr, Kb);
        assemble_rope_kernel<<<nb, 256>>>(qcu, qr, Qb);
    }

    // 4. attention scores per head:  Sc[h] = scale * Q_h @ K_h^T
    const float scale = 1.f / sqrtf((float)DQK);
    gemm_nt(Sc, Qb, Kb, nullptr,
            S_LEN, S_LEN, DQK, NH * DQK, NH * DQK, S_LEN,
            scale, NH, (long long)DQK, (long long)DQK,
            (long long)S_LEN * S_LEN);

    // 5. softmax over keys
    softmax_kernel<<<NH * S_LEN, 256>>>(Sc);

    // 6. ctx[q, h*128+d] = sum_k P[h,q,k] * V[k, h*128+d]
    gemm_nn(ctx, Sc, V, nullptr,
            S_LEN, HD, S_LEN, S_LEN, NH * HD, NH * HD,
            1.f, NH, (long long)S_LEN * S_LEN, (long long)HD, (long long)HD);

    // 7. output projection
    gemm_nt(out, ctx, out_w, out_b, S_LEN, HIDDEN, NH * HD, NH * HD, NH * HD, HIDDEN);
}

// round 5
// speedup vs baseline: 3.1014x; 3.1014x over previous
#include <cuda_runtime.h>
#include <math.h>
#include <stdint.h>

// Problem constants
#define S_LEN   2048
#define HIDDEN  2048
#define NH      16
#define HD      128
#define RD      64
#define KVC     512
#define QCDIM   1024
#define DQK     192   // HD + RD

// ---------------------------------------------------------------------------
// Scratch buffers (static device allocations; no cudaMalloc allowed)
// ---------------------------------------------------------------------------
__device__ float g_kvc[S_LEN * KVC];
__device__ float g_qc [S_LEN * QCDIM];
__device__ float g_kc [S_LEN * NH * HD];
__device__ float g_kr [S_LEN * NH * RD];
__device__ float g_qcu[S_LEN * NH * HD];
__device__ float g_qr [S_LEN * NH * RD];
__device__ float g_Kb [S_LEN * NH * DQK];
__device__ float g_Qb [S_LEN * NH * DQK];
__device__ float g_V  [S_LEN * NH * HD];
__device__ float g_VT [NH * HD * S_LEN];              // per-head V^T [h][d][k]
__device__ float g_Sc [(size_t)NH * S_LEN * S_LEN];   // scores/probs [h, q, k]
__device__ float g_ctx[S_LEN * NH * HD];

// ---------------------------------------------------------------------------
// Helpers
// ---------------------------------------------------------------------------
__device__ __forceinline__ uint32_t smem_u32(const void* p) {
    uint32_t a;
    asm("{ .reg .u64 t; cvta.to.shared.u64 t, %1; cvt.u32.u64 %0, t; }"
        : "=r"(a) : "l"(p));
    return a;
}

__device__ __forceinline__ uint32_t f2tf32(float v) {
    uint32_t u;
    asm("cvt.rna.tf32.f32 %0, %1;" : "=r"(u) : "f"(v));
    return u;
}

#define CP_ASYNC16(dst, src) \
    asm volatile("cp.async.cg.shared.global [%0], [%1], 16;" :: "r"(dst), "l"(src) : "memory")
#define CP_COMMIT() asm volatile("cp.async.commit_group;" ::: "memory")
#define CP_WAIT2()  asm volatile("cp.async.wait_group 2;" ::: "memory")

__device__ __forceinline__ void mma_tf32(float* c, const uint32_t* a, const uint32_t* b) {
    asm volatile(
        "mma.sync.aligned.m16n8k8.row.col.f32.tf32.tf32.f32 "
        "{%0,%1,%2,%3}, {%4,%5,%6,%7}, {%8,%9}, {%0,%1,%2,%3};"
        : "+f"(c[0]), "+f"(c[1]), "+f"(c[2]), "+f"(c[3])
        : "r"(a[0]), "r"(a[1]), "r"(a[2]), "r"(a[3]), "r"(b[0]), "r"(b[1]));
}

// ---------------------------------------------------------------------------
// Tensor-core NT GEMM (mma.sync tf32):  C = alpha * A @ B^T (+ bias)
//   A: [M,K] row-major (lda floats), B: [N,K] row-major (ldb floats)
//   M,N multiples of 128; K multiple of 32. Batched via grid.z strides.
//   256 threads (8 warps, 4x2), CTA tile 128x128, K-tile 32, 3-stage cp.async.
// ---------------------------------------------------------------------------
#define KT        32
#define RS        36                      // padded row stride in floats
#define TILE_F    (128 * RS)              // 4608 floats per matrix tile
#define STAGE_F   (2 * TILE_F)
#define SMEM_BYTES (3 * STAGE_F * 4)      // 110592 bytes

__device__ __forceinline__ void load_tile(
    const float* __restrict__ A, const float* __restrict__ B,
    int mBase, int nBase, int lda, int ldb, int k0,
    uint32_t dstA, uint32_t dstB, int tid)
{
    #pragma unroll
    for (int i = 0; i < 4; ++i) {
        const int idx = i * 256 + tid;     // 0..1023
        const int row = idx >> 3;          // 0..127
        const int seg = idx & 7;           // 16B segment within the 128B of data
        const uint32_t off = (uint32_t)(row * (RS * 4) + seg * 16);
        CP_ASYNC16(dstA + off, A + (long long)(mBase + row) * lda + k0 + seg * 4);
        CP_ASYNC16(dstB + off, B + (long long)(nBase + row) * ldb + k0 + seg * 4);
    }
}

__global__ void __launch_bounds__(256, 2) mma_nt_kernel(
    const float* __restrict__ A, const float* __restrict__ B,
    const float* __restrict__ bias, float* __restrict__ C,
    int K, int lda, int ldb, int ldc,
    long long sA, long long sB, long long sC, float alpha)
{
    extern __shared__ float smem[];
    const uint32_t sb = smem_u32(smem);
    const int tid = threadIdx.x;
    const int wid = tid >> 5;
    const int lane = tid & 31;
    const int g = lane >> 2;       // group id 0..7
    const int t = lane & 3;        // thread-in-group 0..3
    const int warp_m = wid >> 1;   // 0..3 -> 32-row slab
    const int warp_n = wid & 1;    // 0..1 -> 64-col slab

    const int mBase = blockIdx.y * 128;
    const int nBase = blockIdx.x * 128;
    A += (long long)blockIdx.z * sA;
    B += (long long)blockIdx.z * sB;
    C += (long long)blockIdx.z * sC;

    float acc[2][8][4];
    #pragma unroll
    for (int i = 0; i < 2; ++i)
        #pragma unroll
        for (int j = 0; j < 8; ++j)
            #pragma unroll
            for (int q = 0; q < 4; ++q) acc[i][j][q] = 0.f;

    const int T = K / KT;

    // Prefetch first 3 k-tiles
    #pragma unroll
    for (int s = 0; s < 3; ++s) {
        load_tile(A, B, mBase, nBase, lda, ldb, s * KT,
                  sb + s * (STAGE_F * 4),
                  sb + s * (STAGE_F * 4) + TILE_F * 4, tid);
        CP_COMMIT();
    }

    for (int kt = 0; kt < T; ++kt) {
        const int b = kt - (kt / 3) * 3;
        CP_WAIT2();
        __syncthreads();

        const float* As = smem + b * STAGE_F;
        const float* Bs = As + TILE_F;

        #pragma unroll
        for (int ks = 0; ks < 4; ++ks) {
            const int kc = ks * 8 + t;
            uint32_t af[2][4];
            #pragma unroll
            for (int mt = 0; mt < 2; ++mt) {
                const float* ap = As + (warp_m * 32 + mt * 16 + g) * RS + kc;
                af[mt][0] = f2tf32(ap[0]);
                af[mt][1] = f2tf32(ap[8 * RS]);
                af[mt][2] = f2tf32(ap[4]);
                af[mt][3] = f2tf32(ap[8 * RS + 4]);
            }
            uint32_t bf[8][2];
            #pragma unroll
            for (int nt = 0; nt < 8; ++nt) {
                const float* bp = Bs + (warp_n * 64 + nt * 8 + g) * RS + kc;
                bf[nt][0] = f2tf32(bp[0]);
                bf[nt][1] = f2tf32(bp[4]);
            }
            #pragma unroll
            for (int mt = 0; mt < 2; ++mt)
                #pragma unroll
                for (int nt = 0; nt < 8; ++nt)
                    mma_tf32(acc[mt][nt], af[mt], bf[nt]);
        }

        __syncthreads();
        if (kt + 3 < T) {
            load_tile(A, B, mBase, nBase, lda, ldb, (kt + 3) * KT,
                      sb + b * (STAGE_F * 4),
                      sb + b * (STAGE_F * 4) + TILE_F * 4, tid);
        }
        CP_COMMIT();
    }

    // Epilogue: c0,c1 -> (row, col..col+1); c2,c3 -> (row+8, col..col+1)
    #pragma unroll
    for (int mt = 0; mt < 2; ++mt) {
        const long long row0 = mBase + warp_m * 32 + mt * 16 + g;
        #pragma unroll
        for (int nt = 0; nt < 8; ++nt) {
            const int col = nBase + warp_n * 64 + nt * 8 + 2 * t;
            float2 lo, hi;
            lo.x = acc[mt][nt][0] * alpha;
            lo.y = acc[mt][nt][1] * alpha;
            hi.x = acc[mt][nt][2] * alpha;
            hi.y = acc[mt][nt][3] * alpha;
            if (bias) {
                const float b0 = bias[col], b1 = bias[col + 1];
                lo.x += b0; lo.y += b1;
                hi.x += b0; hi.y += b1;
            }
            *(float2*)(C + row0 * (long long)ldc + col)       = lo;
            *(float2*)(C + (row0 + 8) * (long long)ldc + col) = hi;
        }
    }
}

// ---------------------------------------------------------------------------
// Assemble concat buffer [s, h, 192]: cols 0..127 from comp, 128..191 roped.
// RoPE positions = head index (faithful to reference's axis choice).
// ---------------------------------------------------------------------------
__global__ void assemble_rope_kernel(const float* __restrict__ comp,
                                     const float* __restrict__ rope,
                                     float* __restrict__ out)
{
    const int idx = blockIdx.x * blockDim.x + threadIdx.x;
    if (idx >= S_LEN * NH * DQK) return;
    const int s = idx / (NH * DQK);
    const int c = idx - s * (NH * DQK);
    const int h = c / DQK;
    const int d = c - h * DQK;
    float val;
    if (d < HD) {
        val = comp[s * (NH * HD) + h * HD + d];
    } else {
        const int r = d - HD;
        const int j = r >> 1;
        const float inv_freq = powf(10000.f, -(2.f * j) / (float)RD);
        const float ang = (float)h * inv_freq;
        const float sn = sinf(ang), cs = cosf(ang);
        const int base = s * (NH * RD) + h * RD + 2 * j;
        const float x1 = rope[base];
        const float x2 = rope[base + 1];
        val = (r & 1) ? (x1 * sn + x2 * cs) : (x1 * cs - x2 * sn);
    }
    out[idx] = val;
}

// ---------------------------------------------------------------------------
// V transpose: VT[h*HD + d][k] = V[k][h*HD + d]   (both 2048x2048 fp32)
// ---------------------------------------------------------------------------
__global__ void transpose_kernel(const float* __restrict__ V, float* __restrict__ VT)
{
    __shared__ float tbuf[32][33];
    const int bx = blockIdx.x * 32;   // column (h*HD+d) base
    const int by = blockIdx.y * 32;   // row (k) base
    const int x = threadIdx.x, y = threadIdx.y;
    #pragma unroll
    for (int i = 0; i < 32; i += 8)
        tbuf[y + i][x] = V[(long long)(by + y + i) * (NH * HD) + bx + x];
    __syncthreads();
    #pragma unroll
    for (int i = 0; i < 32; i += 8)
        VT[(long long)(bx + y + i) * S_LEN + by + x] = tbuf[x][y + i];
}

// ---------------------------------------------------------------------------
// Row softmax over S_LEN=2048 elements. One 256-thread block per row.
// ---------------------------------------------------------------------------
__global__ void softmax_kernel(float* __restrict__ Sc)
{
    float* p = Sc + (long long)blockIdx.x * S_LEN;
    const int tid = threadIdx.x;
    __shared__ float red[256];

    float v[8];
    float lm = -INFINITY;
    #pragma unroll
    for (int i = 0; i < 8; i++) {
        v[i] = p[tid + i * 256];
        lm = fmaxf(lm, v[i]);
    }
    red[tid] = lm;
    __syncthreads();
    #pragma unroll
    for (int s = 128; s > 0; s >>= 1) {
        if (tid < s) red[tid] = fmaxf(red[tid], red[tid + s]);
        __syncthreads();
    }
    const float m = red[0];
    __syncthreads();

    float ls = 0.f;
    #pragma unroll
    for (int i = 0; i < 8; i++) {
        v[i] = expf(v[i] - m);
        ls += v[i];
    }
    red[tid] = ls;
    __syncthreads();
    #pragma unroll
    for (int s = 128; s > 0; s >>= 1) {
        if (tid < s) red[tid] += red[tid + s];
        __syncthreads();
    }
    const float inv = 1.f / red[0];
    #pragma unroll
    for (int i = 0; i < 8; i++) p[tid + i * 256] = v[i] * inv;
}

// ---------------------------------------------------------------------------
// Host-side launch helper
// ---------------------------------------------------------------------------
static void gemm_nt(float* C, const float* A, const float* B, const float* bias,
                    int M, int N, int K, int lda, int ldb, int ldc,
                    float alpha = 1.f, int batch = 1,
                    long long sA = 0, long long sB = 0, long long sC = 0)
{
    dim3 grid(N / 128, M / 128, batch);
    mma_nt_kernel<<<grid, 256, SMEM_BYTES>>>(A, B, bias, C, K, lda, ldb, ldc,
                                             sA, sB, sC, alpha);
}

extern "C" void kernel_launch(void* const* d_in, const int* in_sizes, int n_in,
                              void* d_out, int out_size)
{
    const float* x            = (const float*)d_in[0];
    const float* kv_down_w    = (const float*)d_in[1];
    const float* kv_down_b    = (const float*)d_in[2];
    const float* key_up_w     = (const float*)d_in[3];
    const float* key_up_b     = (const float*)d_in[4];
    const float* value_up_w   = (const float*)d_in[5];
    const float* value_up_b   = (const float*)d_in[6];
    const float* key_rope_w   = (const float*)d_in[7];
    const float* key_rope_b   = (const float*)d_in[8];
    const float* query_down_w = (const float*)d_in[9];
    const float* query_down_b = (const float*)d_in[10];
    const float* query_up_w   = (const float*)d_in[11];
    const float* query_up_b   = (const float*)d_in[12];
    const float* query_rope_w = (const float*)d_in[13];
    const float* query_rope_b = (const float*)d_in[14];
    const float* out_w        = (const float*)d_in[15];
    const float* out_b        = (const float*)d_in[16];
    float* out = (float*)d_out;

    cudaFuncSetAttribute(mma_nt_kernel,
                         cudaFuncAttributeMaxDynamicSharedMemorySize, SMEM_BYTES);

    float *kvc, *qc, *kc, *kr, *qcu, *qr, *Kb, *Qb, *V, *VT, *Sc, *ctx;
    cudaGetSymbolAddress((void**)&kvc, g_kvc);
    cudaGetSymbolAddress((void**)&qc,  g_qc);
    cudaGetSymbolAddress((void**)&kc,  g_kc);
    cudaGetSymbolAddress((void**)&kr,  g_kr);
    cudaGetSymbolAddress((void**)&qcu, g_qcu);
    cudaGetSymbolAddress((void**)&qr,  g_qr);
    cudaGetSymbolAddress((void**)&Kb,  g_Kb);
    cudaGetSymbolAddress((void**)&Qb,  g_Qb);
    cudaGetSymbolAddress((void**)&V,   g_V);
    cudaGetSymbolAddress((void**)&VT,  g_VT);
    cudaGetSymbolAddress((void**)&Sc,  g_Sc);
    cudaGetSymbolAddress((void**)&ctx, g_ctx);

    // 1. down projections
    gemm_nt(kvc, x, kv_down_w, kv_down_b, S_LEN, KVC,   HIDDEN, HIDDEN, HIDDEN, KVC);
    gemm_nt(qc,  x, query_down_w, query_down_b, S_LEN, QCDIM, HIDDEN, HIDDEN, HIDDEN, QCDIM);

    // 2. up projections
    gemm_nt(kc,  kvc, key_up_w,     key_up_b,     S_LEN, NH * HD, KVC,   KVC,   KVC,   NH * HD);
    gemm_nt(V,   kvc, value_up_w,   value_up_b,   S_LEN, NH * HD, KVC,   KVC,   KVC,   NH * HD);
    gemm_nt(kr,  kvc, key_rope_w,   key_rope_b,   S_LEN, NH * RD, KVC,   KVC,   KVC,   NH * RD);
    gemm_nt(qcu, qc,  query_up_w,   query_up_b,   S_LEN, NH * HD, QCDIM, QCDIM, QCDIM, NH * HD);
    gemm_nt(qr,  qc,  query_rope_w, query_rope_b, S_LEN, NH * RD, QCDIM, QCDIM, QCDIM, NH * RD);

    // 3. rope + concat into [s, h, 192]; transpose V
    {
        const int total = S_LEN * NH * DQK;
        const int nb = (total + 255) / 256;
        assemble_rope_kernel<<<nb, 256>>>(kc,  kr, Kb);
        assemble_rope_kernel<<<nb, 256>>>(qcu, qr, Qb);
        dim3 tg(64, 64);
        transpose_kernel<<<tg, dim3(32, 8)>>>(V, VT);
    }

    // 4. attention scores per head:  Sc[h] = scale * Q_h @ K_h^T
    const float scale = 1.f / sqrtf((float)DQK);
    gemm_nt(Sc, Qb, Kb, nullptr,
            S_LEN, S_LEN, DQK, NH * DQK, NH * DQK, S_LEN,
            scale, NH, (long long)DQK, (long long)DQK,
            (long long)S_LEN * S_LEN);

    // 5. softmax over keys
    softmax_kernel<<<NH * S_LEN, 256>>>(Sc);

    // 6. ctx[q, h*128+d] = P_h @ VT_h^T   (NT with B = V^T per head)
    gemm_nt(ctx, Sc, VT, nullptr,
            S_LEN, HD, S_LEN, S_LEN, S_LEN, NH * HD,
            1.f, NH, (long long)S_LEN * S_LEN, (long long)HD * S_LEN, (long long)HD);

    // 7. output projection
    gemm_nt(out, ctx, out_w, out_b, S_LEN, HIDDEN, NH * HD, NH * HD, NH * HD, HIDDEN);
}

// round 6
// speedup vs baseline: 3.3377x; 1.0762x over previous
#include <cuda_runtime.h>
#include <math.h>
#include <stdint.h>

// Problem constants
#define S_LEN   2048
#define HIDDEN  2048
#define NH      16
#define HD      128
#define RD      64
#define KVC     512
#define QCDIM   1024
#define DQK     192   // HD + RD

// ---------------------------------------------------------------------------
// Scratch buffers
// ---------------------------------------------------------------------------
__device__ float g_dq [S_LEN * (KVC + QCDIM)];        // [s][1536]: kvc | qc
__device__ float g_kvu[S_LEN * (2*NH*HD + NH*RD)];    // [s][5120]: kc | V | kr
__device__ float g_qu [S_LEN * (NH*HD + NH*RD)];      // [s][3072]: qcu | qr
__device__ float g_Kb [S_LEN * NH * DQK];             // concat K  [s][h*192+d]
__device__ float g_Qb [S_LEN * NH * DQK];             // concat Q
__device__ float g_VT [NH * HD * S_LEN];              // per-head V^T [h*128+d][k]
__device__ float g_ctx[S_LEN * NH * HD];

// ---------------------------------------------------------------------------
// Helpers
// ---------------------------------------------------------------------------
__device__ __forceinline__ uint32_t smem_u32(const void* p) {
    uint32_t a;
    asm("{ .reg .u64 t; cvta.to.shared.u64 t, %1; cvt.u32.u64 %0, t; }"
        : "=r"(a) : "l"(p));
    return a;
}
__device__ __forceinline__ uint32_t f2tf32(float v) {
    uint32_t u;
    asm("cvt.rna.tf32.f32 %0, %1;" : "=r"(u) : "f"(v));
    return u;
}
#define CP_ASYNC16(dst, src) \
    asm volatile("cp.async.cg.shared.global [%0], [%1], 16;" :: "r"(dst), "l"(src) : "memory")
#define CP_COMMIT() asm volatile("cp.async.commit_group;" ::: "memory")
#define CP_WAIT0()  asm volatile("cp.async.wait_group 0;" ::: "memory")
#define CP_WAIT1()  asm volatile("cp.async.wait_group 1;" ::: "memory")
#define CP_WAIT2()  asm volatile("cp.async.wait_group 2;" ::: "memory")

__device__ __forceinline__ void mma_tf32(float* c, const uint32_t* a, const uint32_t* b) {
    asm volatile(
        "mma.sync.aligned.m16n8k8.row.col.f32.tf32.tf32.f32 "
        "{%0,%1,%2,%3}, {%4,%5,%6,%7}, {%8,%9}, {%0,%1,%2,%3};"
        : "+f"(c[0]), "+f"(c[1]), "+f"(c[2]), "+f"(c[3])
        : "r"(a[0]), "r"(a[1]), "r"(a[2]), "r"(a[3]), "r"(b[0]), "r"(b[1]));
}

// ---------------------------------------------------------------------------
// Segmented-B tensor-core NT GEMM:  C[:, seg] = A @ Bseg^T + biasseg
//   A: [M, K] row-major (lda). Up to 3 B segments, each [Nseg, K] (ldb = K).
//   Segment boundaries n1, n2 are multiples of 128. C row-major (ldc = Ntot).
// ---------------------------------------------------------------------------
#define KT        32
#define RS        36
#define TILE_F    (128 * RS)
#define STAGE_F   (2 * TILE_F)
#define SMEM_BYTES (3 * STAGE_F * 4)      // 110592

__device__ __forceinline__ void load_tile(
    const float* __restrict__ A, const float* __restrict__ B,
    int mBase, int nLoc, int lda, int ldb, int k0,
    uint32_t dstA, uint32_t dstB, int tid)
{
    #pragma unroll
    for (int i = 0; i < 4; ++i) {
        const int idx = i * 256 + tid;
        const int row = idx >> 3;
        const int seg = idx & 7;
        const uint32_t off = (uint32_t)(row * (RS * 4) + seg * 16);
        CP_ASYNC16(dstA + off, A + (long long)(mBase + row) * lda + k0 + seg * 4);
        CP_ASYNC16(dstB + off, B + (long long)(nLoc + row) * ldb + k0 + seg * 4);
    }
}

__global__ void __launch_bounds__(256, 2) mma_nt_kernel(
    const float* __restrict__ A,
    const float* __restrict__ B0, const float* __restrict__ B1,
    const float* __restrict__ B2,
    const float* __restrict__ bias0, const float* __restrict__ bias1,
    const float* __restrict__ bias2,
    int n1, int n2,
    float* __restrict__ C,
    int K, int lda, int ldc)
{
    extern __shared__ float smem[];
    const uint32_t sb = smem_u32(smem);
    const int tid = threadIdx.x;
    const int wid = tid >> 5;
    const int lane = tid & 31;
    const int g = lane >> 2;
    const int t = lane & 3;
    const int warp_m = wid >> 1;
    const int warp_n = wid & 1;

    const int mBase = blockIdx.y * 128;
    const int nBase = blockIdx.x * 128;

    const float* B; const float* bp; int nLoc;
    if (nBase >= n2)      { B = B2; bp = bias2; nLoc = nBase - n2; }
    else if (nBase >= n1) { B = B1; bp = bias1; nLoc = nBase - n1; }
    else                  { B = B0; bp = bias0; nLoc = nBase; }
    const int ldb = K;

    float acc[2][8][4];
    #pragma unroll
    for (int i = 0; i < 2; ++i)
        #pragma unroll
        for (int j = 0; j < 8; ++j)
            #pragma unroll
            for (int q = 0; q < 4; ++q) acc[i][j][q] = 0.f;

    const int T = K / KT;
    #pragma unroll
    for (int s = 0; s < 3; ++s) {
        load_tile(A, B, mBase, nLoc, lda, ldb, s * KT,
                  sb + s * (STAGE_F * 4),
                  sb + s * (STAGE_F * 4) + TILE_F * 4, tid);
        CP_COMMIT();
    }

    for (int kt = 0; kt < T; ++kt) {
        const int b = kt - (kt / 3) * 3;
        CP_WAIT2();
        __syncthreads();

        const float* As = smem + b * STAGE_F;
        const float* Bs = As + TILE_F;

        #pragma unroll
        for (int ks = 0; ks < 4; ++ks) {
            const int kc = ks * 8 + t;
            uint32_t af[2][4];
            #pragma unroll
            for (int mt = 0; mt < 2; ++mt) {
                const float* ap = As + (warp_m * 32 + mt * 16 + g) * RS + kc;
                af[mt][0] = f2tf32(ap[0]);
                af[mt][1] = f2tf32(ap[8 * RS]);
                af[mt][2] = f2tf32(ap[4]);
                af[mt][3] = f2tf32(ap[8 * RS + 4]);
            }
            uint32_t bf[8][2];
            #pragma unroll
            for (int nt = 0; nt < 8; ++nt) {
                const float* bpr = Bs + (warp_n * 64 + nt * 8 + g) * RS + kc;
                bf[nt][0] = f2tf32(bpr[0]);
                bf[nt][1] = f2tf32(bpr[4]);
            }
            #pragma unroll
            for (int mt = 0; mt < 2; ++mt)
                #pragma unroll
                for (int nt = 0; nt < 8; ++nt)
                    mma_tf32(acc[mt][nt], af[mt], bf[nt]);
        }

        __syncthreads();
        if (kt + 3 < T) {
            load_tile(A, B, mBase, nLoc, lda, ldb, (kt + 3) * KT,
                      sb + b * (STAGE_F * 4),
                      sb + b * (STAGE_F * 4) + TILE_F * 4, tid);
        }
        CP_COMMIT();
    }

    #pragma unroll
    for (int mt = 0; mt < 2; ++mt) {
        const long long row0 = mBase + warp_m * 32 + mt * 16 + g;
        #pragma unroll
        for (int nt = 0; nt < 8; ++nt) {
            const int colLoc = warp_n * 64 + nt * 8 + 2 * t;
            const int col = nBase + colLoc;
            float2 lo, hi;
            const float b0 = bp[nLoc + colLoc], b1 = bp[nLoc + colLoc + 1];
            lo.x = acc[mt][nt][0] + b0;
            lo.y = acc[mt][nt][1] + b1;
            hi.x = acc[mt][nt][2] + b0;
            hi.y = acc[mt][nt][3] + b1;
            *(float2*)(C + row0 * (long long)ldc + col)       = lo;
            *(float2*)(C + (row0 + 8) * (long long)ldc + col) = hi;
        }
    }
}

// ---------------------------------------------------------------------------
// Fused flash attention: per CTA one head, 128 q-rows.
//   Qb/Kb: [s][h*192 + d], VT: [h*128+d][k], out ctx: [s][h*128+d]
// ---------------------------------------------------------------------------
#define RSQ 196
#define RSK 36
#define RSV 132
#define QS_F (128 * RSQ)            // 25088
#define KS_F (128 * RSK)            // 4608 (one buffer)
#define VS_F (128 * RSV)            // 16896
#define OFFK0 QS_F
#define OFFK1 (QS_F + KS_F)
#define OFFV  (QS_F + 2 * KS_F)
#define FL_SMEM_BYTES ((QS_F + 2 * KS_F + VS_F) * 4)   // 204800

__device__ __forceinline__ void fl_load_k(uint32_t dstB, const float* __restrict__ Kb,
                                          int h, int kBase, int c, int tid) {
    #pragma unroll
    for (int i = 0; i < 4; ++i) {
        const int idx = i * 256 + tid;
        const int row = idx >> 3;
        const int seg = idx & 7;
        CP_ASYNC16(dstB + (uint32_t)(row * (RSK * 4) + seg * 16),
                   Kb + (long long)(kBase + row) * (NH * DQK) + h * DQK + c * 32 + seg * 4);
    }
    CP_COMMIT();
}

__device__ __forceinline__ void fl_load_v(uint32_t dstB, const float* __restrict__ VTp,
                                          int h, int kBase, int tid) {
    #pragma unroll
    for (int i = 0; i < 16; ++i) {
        const int idx = i * 256 + tid;
        const int row = idx >> 5;
        const int seg = idx & 31;
        CP_ASYNC16(dstB + (uint32_t)(row * (RSV * 4) + seg * 16),
                   VTp + (long long)(h * HD + row) * S_LEN + kBase + seg * 4);
    }
    CP_COMMIT();
}

__global__ void __launch_bounds__(256) flash_kernel(
    const float* __restrict__ Qb, const float* __restrict__ Kb,
    const float* __restrict__ VTp, float* __restrict__ ctx)
{
    extern __shared__ float fsm[];
    const uint32_t sb = smem_u32(fsm);
    const int tid = threadIdx.x;
    const int w = tid >> 5;
    const int lane = tid & 31;
    const int g = lane >> 2;
    const int t = lane & 3;
    const int qBase = blockIdx.x * 128;
    const int h = blockIdx.y;
    const float scale = rsqrtf((float)DQK);

    float Sacc[16][4];
    float Oacc[16][4];
    #pragma unroll
    for (int nt = 0; nt < 16; ++nt)
        #pragma unroll
        for (int i = 0; i < 4; ++i) Oacc[nt][i] = 0.f;
    float m0 = -INFINITY, m1 = -INFINITY, l0 = 0.f, l1 = 0.f;

    // Prologue: issue Q tile + K(0,0)
    #pragma unroll
    for (int i = 0; i < 24; ++i) {
        const int idx = i * 256 + tid;
        const int row = idx / 48;
        const int seg = idx % 48;
        CP_ASYNC16(sb + (uint32_t)(row * (RSQ * 4) + seg * 16),
                   Qb + (long long)(qBase + row) * (NH * DQK) + h * DQK + seg * 4);
    }
    CP_COMMIT();
    fl_load_k(sb + OFFK0 * 4, Kb, h, 0, 0, tid);
    CP_WAIT0();
    __syncthreads();
    // cvt Q (with softmax scale folded in)
    for (int i = tid; i < QS_F; i += 256) {
        fsm[i] = __uint_as_float(f2tf32(fsm[i] * scale));
    }
    __syncthreads();

    for (int j = 0; j < 16; ++j) {
        const int kBase = j * 128;
        #pragma unroll
        for (int nt = 0; nt < 16; ++nt)
            #pragma unroll
            for (int i = 0; i < 4; ++i) Sacc[nt][i] = 0.f;

        #pragma unroll 1
        for (int c = 0; c < 6; ++c) {
            if (c == 1) { CP_WAIT1(); } else { CP_WAIT0(); }
            __syncthreads();
            // issue next loads
            if (c == 0) {
                fl_load_k(sb + OFFK1 * 4, Kb, h, kBase, 1, tid);
                fl_load_v(sb + OFFV * 4, VTp, h, kBase, tid);
            } else if (c < 5) {
                fl_load_k(sb + (((c + 1) & 1) ? OFFK1 : OFFK0) * 4, Kb, h, kBase, c + 1, tid);
            } else if (j < 15) {
                fl_load_k(sb + OFFK0 * 4, Kb, h, kBase + 128, 0, tid);
            }
            // cvt current K chunk
            const int kOff = (c & 1) ? OFFK1 : OFFK0;
            #pragma unroll
            for (int i = 0; i < 18; ++i) {
                const int idx = i * 256 + tid;
                fsm[kOff + idx] = __uint_as_float(f2tf32(fsm[kOff + idx]));
            }
            __syncthreads();
            // S += Q @ Kc^T
            #pragma unroll
            for (int s = 0; s < 4; ++s) {
                const float* ap = fsm + (w * 16 + g) * RSQ + c * 32 + s * 8 + t;
                uint32_t a[4];
                a[0] = __float_as_uint(ap[0]);
                a[1] = __float_as_uint(ap[8 * RSQ]);
                a[2] = __float_as_uint(ap[4]);
                a[3] = __float_as_uint(ap[8 * RSQ + 4]);
                const float* bb = fsm + kOff + g * RSK + s * 8 + t;
                #pragma unroll
                for (int nt = 0; nt < 16; ++nt) {
                    uint32_t b[2];
                    b[0] = __float_as_uint(bb[nt * 8 * RSK]);
                    b[1] = __float_as_uint(bb[nt * 8 * RSK + 4]);
                    mma_tf32(Sacc[nt], a, b);
                }
            }
        }

        // --- online softmax (rows g and g+8 of this warp's 16) ---
        float bm0 = -INFINITY, bm1 = -INFINITY;
        #pragma unroll
        for (int nt = 0; nt < 16; ++nt) {
            bm0 = fmaxf(bm0, fmaxf(Sacc[nt][0], Sacc[nt][1]));
            bm1 = fmaxf(bm1, fmaxf(Sacc[nt][2], Sacc[nt][3]));
        }
        bm0 = fmaxf(bm0, __shfl_xor_sync(0xffffffffu, bm0, 1));
        bm0 = fmaxf(bm0, __shfl_xor_sync(0xffffffffu, bm0, 2));
        bm1 = fmaxf(bm1, __shfl_xor_sync(0xffffffffu, bm1, 1));
        bm1 = fmaxf(bm1, __shfl_xor_sync(0xffffffffu, bm1, 2));
        const float mn0 = fmaxf(m0, bm0), mn1 = fmaxf(m1, bm1);
        const float f0 = __expf(m0 - mn0), f1 = __expf(m1 - mn1);
        m0 = mn0; m1 = mn1;
        float s0 = 0.f, s1 = 0.f;
        #pragma unroll
        for (int nt = 0; nt < 16; ++nt) {
            float p0 = __expf(Sacc[nt][0] - mn0);
            float p1 = __expf(Sacc[nt][1] - mn0);
            float p2 = __expf(Sacc[nt][2] - mn1);
            float p3 = __expf(Sacc[nt][3] - mn1);
            s0 += p0 + p1;
            s1 += p2 + p3;
            Sacc[nt][0] = __uint_as_float(f2tf32(p0));
            Sacc[nt][1] = __uint_as_float(f2tf32(p1));
            Sacc[nt][2] = __uint_as_float(f2tf32(p2));
            Sacc[nt][3] = __uint_as_float(f2tf32(p3));
        }
        s0 += __shfl_xor_sync(0xffffffffu, s0, 1);
        s0 += __shfl_xor_sync(0xffffffffu, s0, 2);
        s1 += __shfl_xor_sync(0xffffffffu, s1, 1);
        s1 += __shfl_xor_sync(0xffffffffu, s1, 2);
        l0 = l0 * f0 + s0;
        l1 = l1 * f1 + s1;
        #pragma unroll
        for (int nt = 0; nt < 16; ++nt) {
            Oacc[nt][0] *= f0; Oacc[nt][1] *= f0;
            Oacc[nt][2] *= f1; Oacc[nt][3] *= f1;
        }

        // cvt V tile (arrived; made visible by the c==2 syncthreads)
        #pragma unroll
        for (int i = 0; i < 66; ++i) {
            const int idx = i * 256 + tid;
            fsm[OFFV + idx] = __uint_as_float(f2tf32(fsm[OFFV + idx]));
        }
        __syncthreads();

        // --- O += P @ V ---
        const int srcA = (lane & ~3) | (t >> 1);
        const int srcB = srcA + 2;
        #pragma unroll
        for (int kc = 0; kc < 16; ++kc) {
            const float v00 = __shfl_sync(0xffffffffu, Sacc[kc][0], srcA);
            const float v01 = __shfl_sync(0xffffffffu, Sacc[kc][1], srcA);
            const float v10 = __shfl_sync(0xffffffffu, Sacc[kc][0], srcB);
            const float v11 = __shfl_sync(0xffffffffu, Sacc[kc][1], srcB);
            const float w00 = __shfl_sync(0xffffffffu, Sacc[kc][2], srcA);
            const float w01 = __shfl_sync(0xffffffffu, Sacc[kc][3], srcA);
            const float w10 = __shfl_sync(0xffffffffu, Sacc[kc][2], srcB);
            const float w11 = __shfl_sync(0xffffffffu, Sacc[kc][3], srcB);
            uint32_t a[4];
            a[0] = __float_as_uint((t & 1) ? v01 : v00);
            a[1] = __float_as_uint((t & 1) ? w01 : w00);
            a[2] = __float_as_uint((t & 1) ? v11 : v10);
            a[3] = __float_as_uint((t & 1) ? w11 : w10);
            const float* vb = fsm + OFFV + g * RSV + kc * 8 + t;
            #pragma unroll
            for (int nt = 0; nt < 16; ++nt) {
                uint32_t b[2];
                b[0] = __float_as_uint(vb[nt * 8 * RSV]);
                b[1] = __float_as_uint(vb[nt * 8 * RSV + 4]);
                mma_tf32(Oacc[nt], a, b);
            }
        }
        // next block's first issue is preceded by wait+syncthreads, so Vs/Ks
        // reuse is safe without an extra barrier here.
    }

    // Epilogue: normalize and write ctx
    const float il0 = 1.f / l0, il1 = 1.f / l1;
    const long long q0 = qBase + w * 16 + g;
    #pragma unroll
    for (int nt = 0; nt < 16; ++nt) {
        const int col = h * HD + nt * 8 + 2 * t;
        float2 lo, hi;
        lo.x = Oacc[nt][0] * il0; lo.y = Oacc[nt][1] * il0;
        hi.x = Oacc[nt][2] * il1; hi.y = Oacc[nt][3] * il1;
        *(float2*)(ctx + q0 * (NH * HD) + col)       = lo;
        *(float2*)(ctx + (q0 + 8) * (NH * HD) + col) = hi;
    }
}

// ---------------------------------------------------------------------------
// Assemble concat buffer [s, h, 192]: cols 0..127 from comp, 128..191 roped.
// RoPE positions = head index (faithful to reference's axis choice).
// ---------------------------------------------------------------------------
__global__ void assemble_rope_kernel(const float* __restrict__ comp, int comp_ld,
                                     const float* __restrict__ rope, int rope_ld,
                                     float* __restrict__ out)
{
    const int idx = blockIdx.x * blockDim.x + threadIdx.x;
    if (idx >= S_LEN * NH * DQK) return;
    const int s = idx / (NH * DQK);
    const int c = idx - s * (NH * DQK);
    const int h = c / DQK;
    const int d = c - h * DQK;
    float val;
    if (d < HD) {
        val = comp[(long long)s * comp_ld + h * HD + d];
    } else {
        const int r = d - HD;
        const int jj = r >> 1;
        const float inv_freq = powf(10000.f, -(2.f * jj) / (float)RD);
        const float ang = (float)h * inv_freq;
        const float sn = sinf(ang), cs = cosf(ang);
        const long long base = (long long)s * rope_ld + h * RD + 2 * jj;
        const float x1 = rope[base];
        const float x2 = rope[base + 1];
        val = (r & 1) ? (x1 * sn + x2 * cs) : (x1 * cs - x2 * sn);
    }
    out[idx] = val;
}

// ---------------------------------------------------------------------------
// V transpose: VT[h*HD + d][k] = V[k][h*HD + d]; V has row stride src_ld
// ---------------------------------------------------------------------------
__global__ void transpose_kernel(const float* __restrict__ V, int src_ld,
                                 float* __restrict__ VT)
{
    __shared__ float tbuf[32][33];
    const int bx = blockIdx.x * 32;
    const int by = blockIdx.y * 32;
    const int x = threadIdx.x, y = threadIdx.y;
    #pragma unroll
    for (int i = 0; i < 32; i += 8)
        tbuf[y + i][x] = V[(long long)(by + y + i) * src_ld + bx + x];
    __syncthreads();
    #pragma unroll
    for (int i = 0; i < 32; i += 8)
        VT[(long long)(bx + y + i) * S_LEN + by + x] = tbuf[x][y + i];
}

// ---------------------------------------------------------------------------
// Host-side launch helper
// ---------------------------------------------------------------------------
static void gemm_seg(float* C, const float* A, int M, int K, int lda, int Ntot,
                     const float* B0, const float* bias0,
                     const float* B1 = nullptr, const float* bias1 = nullptr, int n1 = 1 << 30,
                     const float* B2 = nullptr, const float* bias2 = nullptr, int n2 = 1 << 30)
{
    dim3 grid(Ntot / 128, M / 128);
    mma_nt_kernel<<<grid, 256, SMEM_BYTES>>>(A, B0, B1, B2, bias0, bias1, bias2,
                                             n1, n2, C, K, lda, Ntot);
}

extern "C" void kernel_launch(void* const* d_in, const int* in_sizes, int n_in,
                              void* d_out, int out_size)
{
    const float* x            = (const float*)d_in[0];
    const float* kv_down_w    = (const float*)d_in[1];
    const float* kv_down_b    = (const float*)d_in[2];
    const float* key_up_w     = (const float*)d_in[3];
    const float* key_up_b     = (const float*)d_in[4];
    const float* value_up_w   = (const float*)d_in[5];
    const float* value_up_b   = (const float*)d_in[6];
    const float* key_rope_w   = (const float*)d_in[7];
    const float* key_rope_b   = (const float*)d_in[8];
    const float* query_down_w = (const float*)d_in[9];
    const float* query_down_b = (const float*)d_in[10];
    const float* query_up_w   = (const float*)d_in[11];
    const float* query_up_b   = (const float*)d_in[12];
    const float* query_rope_w = (const float*)d_in[13];
    const float* query_rope_b = (const float*)d_in[14];
    const float* out_w        = (const float*)d_in[15];
    const float* out_b        = (const float*)d_in[16];
    float* out = (float*)d_out;

    cudaFuncSetAttribute(mma_nt_kernel,
                         cudaFuncAttributeMaxDynamicSharedMemorySize, SMEM_BYTES);
    cudaFuncSetAttribute(flash_kernel,
                         cudaFuncAttributeMaxDynamicSharedMemorySize, FL_SMEM_BYTES);

    float *dq, *kvu, *qu, *Kb, *Qb, *VT, *ctx;
    cudaGetSymbolAddress((void**)&dq,  g_dq);
    cudaGetSymbolAddress((void**)&kvu, g_kvu);
    cudaGetSymbolAddress((void**)&qu,  g_qu);
    cudaGetSymbolAddress((void**)&Kb,  g_Kb);
    cudaGetSymbolAddress((void**)&Qb,  g_Qb);
    cudaGetSymbolAddress((void**)&VT,  g_VT);
    cudaGetSymbolAddress((void**)&ctx, g_ctx);

    const int DQT = KVC + QCDIM;            // 1536
    const int KVU = 2 * NH * HD + NH * RD;  // 5120
    const int QUT = NH * HD + NH * RD;      // 3072

    // 1. merged down projections: dq = [kvc | qc]
    gemm_seg(dq, x, S_LEN, HIDDEN, HIDDEN, DQT,
             kv_down_w, kv_down_b, query_down_w, query_down_b, KVC);

    // 2. merged KV up projections: kvu = [kc | V | kr]
    gemm_seg(kvu, dq, S_LEN, KVC, DQT, KVU,
             key_up_w, key_up_b, value_up_w, value_up_b, NH * HD,
             key_rope_w, key_rope_b, 2 * NH * HD);

    // 3. merged Q up projections: qu = [qcu | qr]
    gemm_seg(qu, dq + KVC, S_LEN, QCDIM, DQT, QUT,
             query_up_w, query_up_b, query_rope_w, query_rope_b, NH * HD);

    // 4. rope + concat; V transpose
    {
        const int total = S_LEN * NH * DQK;
        const int nb = (total + 255) / 256;
        assemble_rope_kernel<<<nb, 256>>>(kvu, KVU, kvu + 2 * NH * HD, KVU, Kb);
        assemble_rope_kernel<<<nb, 256>>>(qu, QUT, qu + NH * HD, QUT, Qb);
        transpose_kernel<<<dim3(64, 64), dim3(32, 8)>>>(kvu + NH * HD, KVU, VT);
    }

    // 5. fused flash attention -> ctx
    flash_kernel<<<dim3(S_LEN / 128, NH), 256, FL_SMEM_BYTES>>>(Qb, Kb, VT, ctx);

    // 6. output projection
    gemm_seg(out, ctx, S_LEN, NH * HD, NH * HD, HIDDEN, out_w, out_b);
}

// round 7
// speedup vs baseline: 3.5880x; 1.0750x over previous
#include <cuda_runtime.h>
#include <math.h>
#include <stdint.h>

// Problem constants
#define S_LEN   2048
#define HIDDEN  2048
#define NH      16
#define HD      128
#define RD      64
#define KVC     512
#define QCDIM   1024
#define DQK     192   // HD + RD

// ---------------------------------------------------------------------------
// Scratch buffers
// ---------------------------------------------------------------------------
__device__ float g_dq [S_LEN * (KVC + QCDIM)];        // [s][1536]: kvc | qc
__device__ float g_kvu[S_LEN * (2*NH*HD + NH*RD)];    // [s][5120]: kc | V | kr
__device__ float g_qu [S_LEN * (NH*HD + NH*RD)];      // [s][3072]: qcu | qr
__device__ float g_Kb [S_LEN * NH * DQK];             // concat K (tf32 bits)
__device__ float g_Qb [S_LEN * NH * DQK];             // concat Q (tf32 bits, scaled)
__device__ float g_VT [NH * HD * S_LEN];              // per-head V^T (tf32 bits)
__device__ float g_ctx[S_LEN * NH * HD];
__device__ float2 g_trig[NH * 32];                    // (cos,sin) per (h, pair)

// ---------------------------------------------------------------------------
// Helpers
// ---------------------------------------------------------------------------
__device__ __forceinline__ uint32_t smem_u32(const void* p) {
    uint32_t a;
    asm("{ .reg .u64 t; cvta.to.shared.u64 t, %1; cvt.u32.u64 %0, t; }"
        : "=r"(a) : "l"(p));
    return a;
}
__device__ __forceinline__ uint32_t f2tf32(float v) {
    uint32_t u;
    asm("cvt.rna.tf32.f32 %0, %1;" : "=r"(u) : "f"(v));
    return u;
}
#define CP_ASYNC16(dst, src) \
    asm volatile("cp.async.cg.shared.global [%0], [%1], 16;" :: "r"(dst), "l"(src) : "memory")
#define CP_COMMIT() asm volatile("cp.async.commit_group;" ::: "memory")
#define CP_WAIT0()  asm volatile("cp.async.wait_group 0;" ::: "memory")
#define CP_WAIT1()  asm volatile("cp.async.wait_group 1;" ::: "memory")
#define CP_WAIT2()  asm volatile("cp.async.wait_group 2;" ::: "memory")

__device__ __forceinline__ void mma_tf32(float* c, const uint32_t* a, const uint32_t* b) {
    asm volatile(
        "mma.sync.aligned.m16n8k8.row.col.f32.tf32.tf32.f32 "
        "{%0,%1,%2,%3}, {%4,%5,%6,%7}, {%8,%9}, {%0,%1,%2,%3};"
        : "+f"(c[0]), "+f"(c[1]), "+f"(c[2]), "+f"(c[3])
        : "r"(a[0]), "r"(a[1]), "r"(a[2]), "r"(a[3]), "r"(b[0]), "r"(b[1]));
}

// ---------------------------------------------------------------------------
// Segmented-B tensor-core NT GEMM (unchanged from round 6, passing)
// ---------------------------------------------------------------------------
#define KT        32
#define RS        36
#define TILE_F    (128 * RS)
#define STAGE_F   (2 * TILE_F)
#define SMEM_BYTES (3 * STAGE_F * 4)      // 110592

__device__ __forceinline__ void load_tile(
    const float* __restrict__ A, const float* __restrict__ B,
    int mBase, int nLoc, int lda, int ldb, int k0,
    uint32_t dstA, uint32_t dstB, int tid)
{
    #pragma unroll
    for (int i = 0; i < 4; ++i) {
        const int idx = i * 256 + tid;
        const int row = idx >> 3;
        const int seg = idx & 7;
        const uint32_t off = (uint32_t)(row * (RS * 4) + seg * 16);
        CP_ASYNC16(dstA + off, A + (long long)(mBase + row) * lda + k0 + seg * 4);
        CP_ASYNC16(dstB + off, B + (long long)(nLoc + row) * ldb + k0 + seg * 4);
    }
}

__global__ void __launch_bounds__(256, 2) mma_nt_kernel(
    const float* __restrict__ A,
    const float* __restrict__ B0, const float* __restrict__ B1,
    const float* __restrict__ B2,
    const float* __restrict__ bias0, const float* __restrict__ bias1,
    const float* __restrict__ bias2,
    int n1, int n2,
    float* __restrict__ C,
    int K, int lda, int ldc)
{
    extern __shared__ float smem[];
    const uint32_t sb = smem_u32(smem);
    const int tid = threadIdx.x;
    const int wid = tid >> 5;
    const int lane = tid & 31;
    const int g = lane >> 2;
    const int t = lane & 3;
    const int warp_m = wid >> 1;
    const int warp_n = wid & 1;

    const int mBase = blockIdx.y * 128;
    const int nBase = blockIdx.x * 128;

    const float* B; const float* bp; int nLoc;
    if (nBase >= n2)      { B = B2; bp = bias2; nLoc = nBase - n2; }
    else if (nBase >= n1) { B = B1; bp = bias1; nLoc = nBase - n1; }
    else                  { B = B0; bp = bias0; nLoc = nBase; }
    const int ldb = K;

    float acc[2][8][4];
    #pragma unroll
    for (int i = 0; i < 2; ++i)
        #pragma unroll
        for (int j = 0; j < 8; ++j)
            #pragma unroll
            for (int q = 0; q < 4; ++q) acc[i][j][q] = 0.f;

    const int T = K / KT;
    #pragma unroll
    for (int s = 0; s < 3; ++s) {
        load_tile(A, B, mBase, nLoc, lda, ldb, s * KT,
                  sb + s * (STAGE_F * 4),
                  sb + s * (STAGE_F * 4) + TILE_F * 4, tid);
        CP_COMMIT();
    }

    for (int kt = 0; kt < T; ++kt) {
        const int b = kt - (kt / 3) * 3;
        CP_WAIT2();
        __syncthreads();

        const float* As = smem + b * STAGE_F;
        const float* Bs = As + TILE_F;

        #pragma unroll
        for (int ks = 0; ks < 4; ++ks) {
            const int kc = ks * 8 + t;
            uint32_t af[2][4];
            #pragma unroll
            for (int mt = 0; mt < 2; ++mt) {
                const float* ap = As + (warp_m * 32 + mt * 16 + g) * RS + kc;
                af[mt][0] = f2tf32(ap[0]);
                af[mt][1] = f2tf32(ap[8 * RS]);
                af[mt][2] = f2tf32(ap[4]);
                af[mt][3] = f2tf32(ap[8 * RS + 4]);
            }
            uint32_t bf[8][2];
            #pragma unroll
            for (int nt = 0; nt < 8; ++nt) {
                const float* bpr = Bs + (warp_n * 64 + nt * 8 + g) * RS + kc;
                bf[nt][0] = f2tf32(bpr[0]);
                bf[nt][1] = f2tf32(bpr[4]);
            }
            #pragma unroll
            for (int mt = 0; mt < 2; ++mt)
                #pragma unroll
                for (int nt = 0; nt < 8; ++nt)
                    mma_tf32(acc[mt][nt], af[mt], bf[nt]);
        }

        __syncthreads();
        if (kt + 3 < T) {
            load_tile(A, B, mBase, nLoc, lda, ldb, (kt + 3) * KT,
                      sb + b * (STAGE_F * 4),
                      sb + b * (STAGE_F * 4) + TILE_F * 4, tid);
        }
        CP_COMMIT();
    }

    #pragma unroll
    for (int mt = 0; mt < 2; ++mt) {
        const long long row0 = mBase + warp_m * 32 + mt * 16 + g;
        #pragma unroll
        for (int nt = 0; nt < 8; ++nt) {
            const int colLoc = warp_n * 64 + nt * 8 + 2 * t;
            const int col = nBase + colLoc;
            float2 lo, hi;
            const float b0 = bp[nLoc + colLoc], b1 = bp[nLoc + colLoc + 1];
            lo.x = acc[mt][nt][0] + b0;
            lo.y = acc[mt][nt][1] + b1;
            hi.x = acc[mt][nt][2] + b0;
            hi.y = acc[mt][nt][3] + b1;
            *(float2*)(C + row0 * (long long)ldc + col)       = lo;
            *(float2*)(C + (row0 + 8) * (long long)ldc + col) = hi;
        }
    }
}

// ---------------------------------------------------------------------------
// Fused flash attention: per CTA one head, 128 q-rows.
//   Inputs are pre-converted tf32 bit patterns (Q pre-scaled). No smem cvt.
// ---------------------------------------------------------------------------
#define RSQ 196
#define RSK 36
#define RSV 132
#define QS_F (128 * RSQ)            // 25088
#define KS_F (128 * RSK)            // 4608 per buffer (3 buffers)
#define VS_F (128 * RSV)            // 16896
#define OFFK0 QS_F
#define OFFK1 (QS_F + KS_F)
#define OFFK2 (QS_F + 2 * KS_F)
#define OFFV  (QS_F + 3 * KS_F)
#define FL_SMEM_BYTES ((QS_F + 3 * KS_F + VS_F) * 4)   // 223232

__device__ __forceinline__ void fl_load_k_nc(uint32_t dstB, const float* __restrict__ Kb,
                                             int h, int kBase, int c, int tid) {
    #pragma unroll
    for (int i = 0; i < 4; ++i) {
        const int idx = i * 256 + tid;
        const int row = idx >> 3;
        const int seg = idx & 7;
        CP_ASYNC16(dstB + (uint32_t)(row * (RSK * 4) + seg * 16),
                   Kb + (long long)(kBase + row) * (NH * DQK) + h * DQK + c * 32 + seg * 4);
    }
}

__device__ __forceinline__ void fl_load_v_nc(uint32_t dstB, const float* __restrict__ VTp,
                                             int h, int kBase, int tid) {
    #pragma unroll
    for (int i = 0; i < 16; ++i) {
        const int idx = i * 256 + tid;
        const int row = idx >> 5;
        const int seg = idx & 31;
        CP_ASYNC16(dstB + (uint32_t)(row * (RSV * 4) + seg * 16),
                   VTp + (long long)(h * HD + row) * S_LEN + kBase + seg * 4);
    }
}

__global__ void __launch_bounds__(256) flash_kernel(
    const float* __restrict__ Qb, const float* __restrict__ Kb,
    const float* __restrict__ VTp, float* __restrict__ ctx)
{
    extern __shared__ float fsm[];
    const uint32_t sb = smem_u32(fsm);
    const int tid = threadIdx.x;
    const int w = tid >> 5;
    const int lane = tid & 31;
    const int g = lane >> 2;
    const int t = lane & 3;
    const int qBase = blockIdx.x * 128;
    const int h = blockIdx.y;

    const uint32_t kBufAddr[3] = { sb + OFFK0 * 4, sb + OFFK1 * 4, sb + OFFK2 * 4 };
    const int      kBufOff[3]  = { OFFK0, OFFK1, OFFK2 };

    float Sacc[16][4];
    float Oacc[16][4];
    #pragma unroll
    for (int nt = 0; nt < 16; ++nt)
        #pragma unroll
        for (int i = 0; i < 4; ++i) Oacc[nt][i] = 0.f;
    float m0 = -INFINITY, m1 = -INFINITY, l0 = 0.f, l1 = 0.f;

    // Prologue: Q tile (group 1), K(0,0) (group 2), K(0,1) (group 3)
    #pragma unroll
    for (int i = 0; i < 24; ++i) {
        const int idx = i * 256 + tid;
        const int row = idx / 48;
        const int seg = idx % 48;
        CP_ASYNC16(sb + (uint32_t)(row * (RSQ * 4) + seg * 16),
                   Qb + (long long)(qBase + row) * (NH * DQK) + h * DQK + seg * 4);
    }
    CP_COMMIT();
    fl_load_k_nc(kBufAddr[0], Kb, h, 0, 0, tid);
    CP_COMMIT();
    fl_load_k_nc(kBufAddr[1], Kb, h, 0, 1, tid);
    CP_COMMIT();

    for (int j = 0; j < 16; ++j) {
        const int kBase = j * 128;
        #pragma unroll
        for (int nt = 0; nt < 16; ++nt)
            #pragma unroll
            for (int i = 0; i < 4; ++i) Sacc[nt][i] = 0.f;

        #pragma unroll
        for (int c = 0; c < 6; ++c) {
            // wait for K(j,c); depth-2 prefetch in flight
            if (c == 5 && j == 15) { CP_WAIT0(); } else { CP_WAIT1(); }
            __syncthreads();
            // issue next loads (after barrier: prior consumers of target bufs done)
            if (c == 0) {
                fl_load_k_nc(kBufAddr[2], Kb, h, kBase, 2, tid);
                fl_load_v_nc(sb + OFFV * 4, VTp, h, kBase, tid);
                CP_COMMIT();
            } else if (c <= 3) {
                fl_load_k_nc(kBufAddr[(c + 2) % 3], Kb, h, kBase, c + 2, tid);
                CP_COMMIT();
            } else if (j < 15) {
                fl_load_k_nc(kBufAddr[c - 4], Kb, h, kBase + 128, c - 4, tid);
                CP_COMMIT();
            }

            // S += Q_chunk @ K_chunk^T
            const int kOff = kBufOff[c % 3];
            #pragma unroll
            for (int s = 0; s < 4; ++s) {
                const float* ap = fsm + (w * 16 + g) * RSQ + c * 32 + s * 8 + t;
                uint32_t a[4];
                a[0] = __float_as_uint(ap[0]);
                a[1] = __float_as_uint(ap[8 * RSQ]);
                a[2] = __float_as_uint(ap[4]);
                a[3] = __float_as_uint(ap[8 * RSQ + 4]);
                const float* bb = fsm + kOff + g * RSK + s * 8 + t;
                #pragma unroll
                for (int nt = 0; nt < 16; ++nt) {
                    uint32_t b[2];
                    b[0] = __float_as_uint(bb[nt * 8 * RSK]);
                    b[1] = __float_as_uint(bb[nt * 8 * RSK + 4]);
                    mma_tf32(Sacc[nt], a, b);
                }
            }
        }

        // --- online softmax (rows g and g+8 of this warp's 16) ---
        float bm0 = -INFINITY, bm1 = -INFINITY;
        #pragma unroll
        for (int nt = 0; nt < 16; ++nt) {
            bm0 = fmaxf(bm0, fmaxf(Sacc[nt][0], Sacc[nt][1]));
            bm1 = fmaxf(bm1, fmaxf(Sacc[nt][2], Sacc[nt][3]));
        }
        bm0 = fmaxf(bm0, __shfl_xor_sync(0xffffffffu, bm0, 1));
        bm0 = fmaxf(bm0, __shfl_xor_sync(0xffffffffu, bm0, 2));
        bm1 = fmaxf(bm1, __shfl_xor_sync(0xffffffffu, bm1, 1));
        bm1 = fmaxf(bm1, __shfl_xor_sync(0xffffffffu, bm1, 2));
        const float mn0 = fmaxf(m0, bm0), mn1 = fmaxf(m1, bm1);
        const float f0 = __expf(m0 - mn0), f1 = __expf(m1 - mn1);
        m0 = mn0; m1 = mn1;
        float s0 = 0.f, s1 = 0.f;
        #pragma unroll
        for (int nt = 0; nt < 16; ++nt) {
            float p0 = __expf(Sacc[nt][0] - mn0);
            float p1 = __expf(Sacc[nt][1] - mn0);
            float p2 = __expf(Sacc[nt][2] - mn1);
            float p3 = __expf(Sacc[nt][3] - mn1);
            s0 += p0 + p1;
            s1 += p2 + p3;
            Sacc[nt][0] = __uint_as_float(f2tf32(p0));
            Sacc[nt][1] = __uint_as_float(f2tf32(p1));
            Sacc[nt][2] = __uint_as_float(f2tf32(p2));
            Sacc[nt][3] = __uint_as_float(f2tf32(p3));
        }
        s0 += __shfl_xor_sync(0xffffffffu, s0, 1);
        s0 += __shfl_xor_sync(0xffffffffu, s0, 2);
        s1 += __shfl_xor_sync(0xffffffffu, s1, 1);
        s1 += __shfl_xor_sync(0xffffffffu, s1, 2);
        l0 = l0 * f0 + s0;
        l1 = l1 * f1 + s1;
        #pragma unroll
        for (int nt = 0; nt < 16; ++nt) {
            Oacc[nt][0] *= f0; Oacc[nt][1] *= f0;
            Oacc[nt][2] *= f1; Oacc[nt][3] *= f1;
        }

        // --- O += P @ V ---  (V ready: guaranteed by chunk-2 wait + barrier)
        const int srcA = (lane & ~3) | (t >> 1);
        const int srcB = srcA + 2;
        #pragma unroll
        for (int kc = 0; kc < 16; ++kc) {
            const float v00 = __shfl_sync(0xffffffffu, Sacc[kc][0], srcA);
            const float v01 = __shfl_sync(0xffffffffu, Sacc[kc][1], srcA);
            const float v10 = __shfl_sync(0xffffffffu, Sacc[kc][0], srcB);
            const float v11 = __shfl_sync(0xffffffffu, Sacc[kc][1], srcB);
            const float w00 = __shfl_sync(0xffffffffu, Sacc[kc][2], srcA);
            const float w01 = __shfl_sync(0xffffffffu, Sacc[kc][3], srcA);
            const float w10 = __shfl_sync(0xffffffffu, Sacc[kc][2], srcB);
            const float w11 = __shfl_sync(0xffffffffu, Sacc[kc][3], srcB);
            uint32_t a[4];
            a[0] = __float_as_uint((t & 1) ? v01 : v00);
            a[1] = __float_as_uint((t & 1) ? w01 : w00);
            a[2] = __float_as_uint((t & 1) ? v11 : v10);
            a[3] = __float_as_uint((t & 1) ? w11 : w10);
            const float* vb = fsm + OFFV + g * RSV + kc * 8 + t;
            #pragma unroll
            for (int nt = 0; nt < 16; ++nt) {
                uint32_t b[2];
                b[0] = __float_as_uint(vb[nt * 8 * RSV]);
                b[1] = __float_as_uint(vb[nt * 8 * RSV + 4]);
                mma_tf32(Oacc[nt], a, b);
            }
        }
    }

    // Epilogue
    const float il0 = 1.f / l0, il1 = 1.f / l1;
    const long long q0 = qBase + w * 16 + g;
    #pragma unroll
    for (int nt = 0; nt < 16; ++nt) {
        const int col = h * HD + nt * 8 + 2 * t;
        float2 lo, hi;
        lo.x = Oacc[nt][0] * il0; lo.y = Oacc[nt][1] * il0;
        hi.x = Oacc[nt][2] * il1; hi.y = Oacc[nt][3] * il1;
        *(float2*)(ctx + q0 * (NH * HD) + col)       = lo;
        *(float2*)(ctx + (q0 + 8) * (NH * HD) + col) = hi;
    }
}

// ---------------------------------------------------------------------------
// Trig table init: (cos,sin) of angle = h * 10000^(-2j/RD) for h in [0,16), j in [0,32)
// ---------------------------------------------------------------------------
__global__ void trig_init_kernel()
{
    const int idx = threadIdx.x;   // 512 threads
    const int h = idx >> 5;
    const int j = idx & 31;
    const float inv_freq = powf(10000.f, -(2.f * j) / (float)RD);
    const float ang = (float)h * inv_freq;
    g_trig[idx] = make_float2(cosf(ang), sinf(ang));
}

// ---------------------------------------------------------------------------
// Assemble concat [s, h, 192], rope via table, output tf32(val * mult)
// ---------------------------------------------------------------------------
__global__ void assemble_rope_kernel(const float* __restrict__ comp, int comp_ld,
                                     const float* __restrict__ rope, int rope_ld,
                                     float* __restrict__ out, float mult)
{
    const int idx = blockIdx.x * blockDim.x + threadIdx.x;
    if (idx >= S_LEN * NH * DQK) return;
    const int s = idx / (NH * DQK);
    const int c = idx - s * (NH * DQK);
    const int h = c / DQK;
    const int d = c - h * DQK;
    float val;
    if (d < HD) {
        val = comp[(long long)s * comp_ld + h * HD + d];
    } else {
        const int r = d - HD;
        const int jj = r >> 1;
        const float2 cs = g_trig[h * 32 + jj];
        const long long base = (long long)s * rope_ld + h * RD + 2 * jj;
        const float x1 = rope[base];
        const float x2 = rope[base + 1];
        val = (r & 1) ? (x1 * cs.y + x2 * cs.x) : (x1 * cs.x - x2 * cs.y);
    }
    out[idx] = __uint_as_float(f2tf32(val * mult));
}

// ---------------------------------------------------------------------------
// V transpose (emits tf32 bits): VT[h*HD + d][k] = tf32(V[k][h*HD + d])
// ---------------------------------------------------------------------------
__global__ void transpose_kernel(const float* __restrict__ V, int src_ld,
                                 float* __restrict__ VT)
{
    __shared__ float tbuf[32][33];
    const int bx = blockIdx.x * 32;
    const int by = blockIdx.y * 32;
    const int x = threadIdx.x, y = threadIdx.y;
    #pragma unroll
    for (int i = 0; i < 32; i += 8)
        tbuf[y + i][x] = V[(long long)(by + y + i) * src_ld + bx + x];
    __syncthreads();
    #pragma unroll
    for (int i = 0; i < 32; i += 8)
        VT[(long long)(bx + y + i) * S_LEN + by + x] =
            __uint_as_float(f2tf32(tbuf[x][y + i]));
}

// ---------------------------------------------------------------------------
// Host-side launch helper
// ---------------------------------------------------------------------------
static void gemm_seg(float* C, const float* A, int M, int K, int lda, int Ntot,
                     const float* B0, const float* bias0,
                     const float* B1 = nullptr, const float* bias1 = nullptr, int n1 = 1 << 30,
                     const float* B2 = nullptr, const float* bias2 = nullptr, int n2 = 1 << 30)
{
    dim3 grid(Ntot / 128, M / 128);
    mma_nt_kernel<<<grid, 256, SMEM_BYTES>>>(A, B0, B1, B2, bias0, bias1, bias2,
                                             n1, n2, C, K, lda, Ntot);
}

extern "C" void kernel_launch(void* const* d_in, const int* in_sizes, int n_in,
                              void* d_out, int out_size)
{
    const float* x            = (const float*)d_in[0];
    const float* kv_down_w    = (const float*)d_in[1];
    const float* kv_down_b    = (const float*)d_in[2];
    const float* key_up_w     = (const float*)d_in[3];
    const float* key_up_b     = (const float*)d_in[4];
    const float* value_up_w   = (const float*)d_in[5];
    const float* value_up_b   = (const float*)d_in[6];
    const float* key_rope_w   = (const float*)d_in[7];
    const float* key_rope_b   = (const float*)d_in[8];
    const float* query_down_w = (const float*)d_in[9];
    const float* query_down_b = (const float*)d_in[10];
    const float* query_up_w   = (const float*)d_in[11];
    const float* query_up_b   = (const float*)d_in[12];
    const float* query_rope_w = (const float*)d_in[13];
    const float* query_rope_b = (const float*)d_in[14];
    const float* out_w        = (const float*)d_in[15];
    const float* out_b        = (const float*)d_in[16];
    float* out = (float*)d_out;

    cudaFuncSetAttribute(mma_nt_kernel,
                         cudaFuncAttributeMaxDynamicSharedMemorySize, SMEM_BYTES);
    cudaFuncSetAttribute(flash_kernel,
                         cudaFuncAttributeMaxDynamicSharedMemorySize, FL_SMEM_BYTES);

    float *dq, *kvu, *qu, *Kb, *Qb, *VT, *ctx;
    cudaGetSymbolAddress((void**)&dq,  g_dq);
    cudaGetSymbolAddress((void**)&kvu, g_kvu);
    cudaGetSymbolAddress((void**)&qu,  g_qu);
    cudaGetSymbolAddress((void**)&Kb,  g_Kb);
    cudaGetSymbolAddress((void**)&Qb,  g_Qb);
    cudaGetSymbolAddress((void**)&VT,  g_VT);
    cudaGetSymbolAddress((void**)&ctx, g_ctx);

    const int DQT = KVC + QCDIM;            // 1536
    const int KVU = 2 * NH * HD + NH * RD;  // 5120
    const int QUT = NH * HD + NH * RD;      // 3072
    const float scale = 1.f / sqrtf((float)DQK);

    trig_init_kernel<<<1, 512>>>();

    // 1. merged down projections: dq = [kvc | qc]
    gemm_seg(dq, x, S_LEN, HIDDEN, HIDDEN, DQT,
             kv_down_w, kv_down_b, query_down_w, query_down_b, KVC);

    // 2. merged KV up projections: kvu = [kc | V | kr]
    gemm_seg(kvu, dq, S_LEN, KVC, DQT, KVU,
             key_up_w, key_up_b, value_up_w, value_up_b, NH * HD,
             key_rope_w, key_rope_b, 2 * NH * HD);

    // 3. merged Q up projections: qu = [qcu | qr]
    gemm_seg(qu, dq + KVC, S_LEN, QCDIM, DQT, QUT,
             query_up_w, query_up_b, query_rope_w, query_rope_b, NH * HD);

    // 4. rope + concat (tf32, Q pre-scaled); V transpose (tf32)
    {
        const int total = S_LEN * NH * DQK;
        const int nb = (total + 255) / 256;
        assemble_rope_kernel<<<nb, 256>>>(kvu, KVU, kvu + 2 * NH * HD, KVU, Kb, 1.f);
        assemble_rope_kernel<<<nb, 256>>>(qu, QUT, qu + NH * HD, QUT, Qb, scale);
        transpose_kernel<<<dim3(64, 64), dim3(32, 8)>>>(kvu + NH * HD, KVU, VT);
    }

    // 5. fused flash attention -> ctx
    flash_kernel<<<dim3(S_LEN / 128, NH), 256, FL_SMEM_BYTES>>>(Qb, Kb, VT, ctx);

    // 6. output projection
    gemm_seg(out, ctx, S_LEN, NH * HD, NH * HD, HIDDEN, out_w, out_b);
}